// round 8
// baseline (speedup 1.0000x reference)
#include <cuda_runtime.h>
#include <cstdint>

// 2-layer GRU encoder, fused, warp-specialized, weights-in-registers, f32x2 FMA.
// R7 -> R8: 256 -> 512 threads/block (4 warps/SMSP) to fix occupancy/issue bound.
// B=1024 batch rows, T=1024 steps, H1=64, H2=32, input feature dim 1.
// Grid: 128 blocks x 512 threads; each block owns 8 batch rows for all T steps.
// Threads 0-255: layer 1 (producer). Threads 256-511: layer 2 (1 step behind).

#define T_STEPS 1024
#define NBATCH  1024
#define H1DIM   64
#define H2DIM   32
#define NB      8      // batch rows per block
#define NTHREADS 512

__device__ __forceinline__ void fma2(uint64_t &acc, uint64_t a, uint64_t b) {
    asm("fma.rn.f32x2 %0, %1, %2, %0;" : "+l"(acc) : "l"(a), "l"(b));
}
__device__ __forceinline__ float hadd2(uint64_t v) {
    float lo, hi;
    asm("mov.b64 {%0,%1}, %2;" : "=f"(lo), "=f"(hi) : "l"(v));
    return lo + hi;
}
__device__ __forceinline__ float sigf(float x) {
    return __fdividef(1.0f, 1.0f + __expf(-x));
}
__device__ __forceinline__ float tanhf_fast(float x) {
    return fmaf(2.0f, sigf(2.0f * x), -1.0f);   // safe at both infinities
}
__device__ __forceinline__ void barrier_all() {
    asm volatile("bar.sync 1, %0;" :: "n"(NTHREADS) : "memory");
}

__global__ void __launch_bounds__(NTHREADS, 1)
gru2_fused_kernel(const float* __restrict__ x,
                  const float* __restrict__ Wih1, const float* __restrict__ Whh1,
                  const float* __restrict__ bih1, const float* __restrict__ bhh1,
                  const float* __restrict__ Wih2, const float* __restrict__ Whh2,
                  const float* __restrict__ bih2, const float* __restrict__ bhh2,
                  float* __restrict__ out)
{
    __shared__ __align__(16) float xs[NB][T_STEPS];      // 32 KB: x slab for this block
    __shared__ __align__(16) float h1s[2][NB][H1DIM];    // double-buffered layer1 state
    __shared__ __align__(16) float h2s[2][NB][H2DIM];    // double-buffered layer2 state

    const int tid = threadIdx.x;
    const int b0  = blockIdx.x * NB;

    // --- load x slab (coalesced float4) + zero h buffers ---
    for (int i = tid; i < NB * T_STEPS / 4; i += NTHREADS) {
        int row = i / (T_STEPS / 4);
        int col = i % (T_STEPS / 4);
        reinterpret_cast<float4*>(xs[row])[col] =
            reinterpret_cast<const float4*>(x + (size_t)(b0 + row) * T_STEPS)[col];
    }
    for (int i = tid; i < 2 * NB * H1DIM; i += NTHREADS) (&h1s[0][0][0])[i] = 0.0f;
    for (int i = tid; i < 2 * NB * H2DIM; i += NTHREADS) (&h2s[0][0][0])[i] = 0.0f;
    __syncthreads();

    if (tid < 256) {
        // ================= LAYER 1 =================
        // thread = (j, kq): j in [0,64), kq in [0,4) splits K=64 into 16-wide slices.
        // lanes 4m..4m+3 share j -> shfl_xor(1), shfl_xor(2) reduce within quad.
        const int kq    = tid & 3;
        const int j     = tid >> 2;
        const int kbase = kq * 16;

        uint64_t w1[3][8];
        #pragma unroll
        for (int g = 0; g < 3; g++) {
            const float* row = Whh1 + (size_t)(j + 64 * g) * 64 + kbase;
            #pragma unroll
            for (int p = 0; p < 8; p++)
                w1[g][p] = *reinterpret_cast<const uint64_t*>(row + 2 * p);
        }
        const float wir = Wih1[j], wiz = Wih1[j + 64], win = Wih1[j + 128];
        const float br  = bih1[j]      + bhh1[j];
        const float bz  = bih1[j + 64] + bhh1[j + 64];
        const float bni = bih1[j + 128];
        const float bnh = bhh1[j + 128];

        int rp = 0;
        for (int it = 0; it <= T_STEPS; ++it) {
            if (it < T_STEPS) {
                uint64_t aR[NB], aZ[NB], aN[NB];
                #pragma unroll
                for (int b = 0; b < NB; b++) { aR[b] = 0; aZ[b] = 0; aN[b] = 0; }

                #pragma unroll
                for (int p = 0; p < 8; p++) {
                    #pragma unroll
                    for (int b = 0; b < NB; b++) {
                        uint64_t hv = *reinterpret_cast<const uint64_t*>(
                            &h1s[rp][b][kbase + 2 * p]);
                        fma2(aR[b], w1[0][p], hv);
                        fma2(aZ[b], w1[1][p], hv);
                        fma2(aN[b], w1[2][p], hv);
                    }
                }
                #pragma unroll
                for (int b = 0; b < NB; b++) {
                    float sR = hadd2(aR[b]);
                    sR += __shfl_xor_sync(0xffffffffu, sR, 1);
                    sR += __shfl_xor_sync(0xffffffffu, sR, 2);
                    float sZ = hadd2(aZ[b]);
                    sZ += __shfl_xor_sync(0xffffffffu, sZ, 1);
                    sZ += __shfl_xor_sync(0xffffffffu, sZ, 2);
                    float sN = hadd2(aN[b]);
                    sN += __shfl_xor_sync(0xffffffffu, sN, 1);
                    sN += __shfl_xor_sync(0xffffffffu, sN, 2);
                    if ((b >> 1) == kq) {        // this thread finalizes 2 batches
                        float xv  = xs[b][it];
                        float r   = sigf(fmaf(wir, xv, sR + br));
                        float z   = sigf(fmaf(wiz, xv, sZ + bz));
                        float gxn = fmaf(win, xv, bni);
                        float n   = tanhf_fast(fmaf(r, sN + bnh, gxn));
                        float ho  = h1s[rp][b][j];
                        h1s[rp ^ 1][b][j] = n + z * (ho - n);
                    }
                }
            }
            barrier_all();
            rp ^= 1;
        }
    } else {
        // ================= LAYER 2 (one step behind) =================
        // thread = (j2, s): j2 in [0,32), s in [0,8) splits K1=64 / K2=32 in eighths.
        // lanes 8m..8m+7 share j2 -> shfl_xor(1), shfl_xor(2), shfl_xor(4).
        const int t2  = tid - 256;
        const int s   = t2 & 7;
        const int j2  = t2 >> 3;
        const int k1b = s * 8;    // slice of h1 (K=64)
        const int k2b = s * 4;    // slice of h2 (K=32)

        uint64_t wI[3][4], wH[3][2];
        #pragma unroll
        for (int g = 0; g < 3; g++) {
            const float* ri = Wih2 + (size_t)(j2 + 32 * g) * 64 + k1b;
            #pragma unroll
            for (int p = 0; p < 4; p++)
                wI[g][p] = *reinterpret_cast<const uint64_t*>(ri + 2 * p);
            const float* rh = Whh2 + (size_t)(j2 + 32 * g) * 32 + k2b;
            #pragma unroll
            for (int p = 0; p < 2; p++)
                wH[g][p] = *reinterpret_cast<const uint64_t*>(rh + 2 * p);
        }
        const float br2  = bih2[j2]      + bhh2[j2];
        const float bz2  = bih2[j2 + 32] + bhh2[j2 + 32];
        const float bn2i = bih2[j2 + 64];
        const float bn2h = bhh2[j2 + 64];

        int rp = 0, q = 0;
        for (int it = 0; it <= T_STEPS; ++it) {
            if (it >= 1) {
                // processes timestep it-1: input h1[it-1] = h1s[rp], state h2s[q]
                uint64_t aR[NB], aZ[NB], aNI[NB], aNH[NB];
                #pragma unroll
                for (int b = 0; b < NB; b++) { aR[b]=0; aZ[b]=0; aNI[b]=0; aNH[b]=0; }

                #pragma unroll
                for (int p = 0; p < 4; p++) {
                    #pragma unroll
                    for (int b = 0; b < NB; b++) {
                        uint64_t hv = *reinterpret_cast<const uint64_t*>(
                            &h1s[rp][b][k1b + 2 * p]);
                        fma2(aR[b],  wI[0][p], hv);
                        fma2(aZ[b],  wI[1][p], hv);
                        fma2(aNI[b], wI[2][p], hv);
                    }
                }
                #pragma unroll
                for (int p = 0; p < 2; p++) {
                    #pragma unroll
                    for (int b = 0; b < NB; b++) {
                        uint64_t hv = *reinterpret_cast<const uint64_t*>(
                            &h2s[q][b][k2b + 2 * p]);
                        fma2(aR[b],  wH[0][p], hv);
                        fma2(aZ[b],  wH[1][p], hv);
                        fma2(aNH[b], wH[2][p], hv);
                    }
                }
                #pragma unroll
                for (int b = 0; b < NB; b++) {
                    float sR  = hadd2(aR[b]);
                    sR  += __shfl_xor_sync(0xffffffffu, sR, 1);
                    sR  += __shfl_xor_sync(0xffffffffu, sR, 2);
                    sR  += __shfl_xor_sync(0xffffffffu, sR, 4);
                    float sZ  = hadd2(aZ[b]);
                    sZ  += __shfl_xor_sync(0xffffffffu, sZ, 1);
                    sZ  += __shfl_xor_sync(0xffffffffu, sZ, 2);
                    sZ  += __shfl_xor_sync(0xffffffffu, sZ, 4);
                    float sNI = hadd2(aNI[b]);
                    sNI += __shfl_xor_sync(0xffffffffu, sNI, 1);
                    sNI += __shfl_xor_sync(0xffffffffu, sNI, 2);
                    sNI += __shfl_xor_sync(0xffffffffu, sNI, 4);
                    float sNH = hadd2(aNH[b]);
                    sNH += __shfl_xor_sync(0xffffffffu, sNH, 1);
                    sNH += __shfl_xor_sync(0xffffffffu, sNH, 2);
                    sNH += __shfl_xor_sync(0xffffffffu, sNH, 4);
                    if (b == s) {                // this thread finalizes 1 batch
                        float r  = sigf(sR + br2);
                        float z  = sigf(sZ + bz2);
                        float n  = tanhf_fast(sNI + bn2i + r * (sNH + bn2h));
                        float ho = h2s[q][b][j2];
                        float hn = n + z * (ho - n);
                        h2s[q ^ 1][b][j2] = hn;
                        if (it == T_STEPS)
                            out[(size_t)(b0 + b) * H2DIM + j2] = hn;
                    }
                }
            }
            barrier_all();
            rp ^= 1;
            q  ^= 1;
        }
    }
}

extern "C" void kernel_launch(void* const* d_in, const int* in_sizes, int n_in,
                              void* d_out, int out_size) {
    const float* x    = (const float*)d_in[0];   // [1024,1024]
    const float* Wih1 = (const float*)d_in[1];   // [192,1]
    const float* Whh1 = (const float*)d_in[2];   // [192,64]
    const float* bih1 = (const float*)d_in[3];   // [192]
    const float* bhh1 = (const float*)d_in[4];   // [192]
    const float* Wih2 = (const float*)d_in[5];   // [96,64]
    const float* Whh2 = (const float*)d_in[6];   // [96,32]
    const float* bih2 = (const float*)d_in[7];   // [96]
    const float* bhh2 = (const float*)d_in[8];   // [96]
    float* out = (float*)d_out;                  // [1024,32]

    gru2_fused_kernel<<<NBATCH / NB, NTHREADS>>>(
        x, Wih1, Whh1, bih1, bhh1, Wih2, Whh2, bih2, bhh2, out);
}

// round 9
// speedup vs baseline: 1.6040x; 1.6040x over previous
#include <cuda_runtime.h>
#include <cstdint>

// 2-layer GRU encoder, fused, warp-specialized, weights-in-registers, f32x2 FMA.
// R9: 2 CTAs/SM (4 warps/SMSP) via NB=4 + grid=256 + __launch_bounds__(256,2).
//     Registers kept <128 (no spills) by making the batch loop outer (small accs).
//     k-slices interleaved (kh+2p / s+4p) -> conflict-free smem h loads.
// B=1024 batch rows, T=1024 steps, H1=64, H2=32, input feature dim 1.
// Threads 0-127: layer 1 (producer). Threads 128-255: layer 2 (1 step behind).

#define T_STEPS 1024
#define NBATCH  1024
#define H1DIM   64
#define H2DIM   32
#define NB      4      // batch rows per block
#define NTHREADS 256

__device__ __forceinline__ void fma2(uint64_t &acc, uint64_t a, uint64_t b) {
    asm("fma.rn.f32x2 %0, %1, %2, %0;" : "+l"(acc) : "l"(a), "l"(b));
}
__device__ __forceinline__ float hadd2(uint64_t v) {
    float lo, hi;
    asm("mov.b64 {%0,%1}, %2;" : "=f"(lo), "=f"(hi) : "l"(v));
    return lo + hi;
}
__device__ __forceinline__ float sigf(float x) {
    return __fdividef(1.0f, 1.0f + __expf(-x));
}
__device__ __forceinline__ float tanhf_fast(float x) {
    return fmaf(2.0f, sigf(2.0f * x), -1.0f);   // safe at both infinities
}
__device__ __forceinline__ void barrier_all() {
    asm volatile("bar.sync 1, %0;" :: "n"(NTHREADS) : "memory");
}

__global__ void __launch_bounds__(NTHREADS, 2)
gru2_fused_kernel(const float* __restrict__ x,
                  const float* __restrict__ Wih1, const float* __restrict__ Whh1,
                  const float* __restrict__ bih1, const float* __restrict__ bhh1,
                  const float* __restrict__ Wih2, const float* __restrict__ Whh2,
                  const float* __restrict__ bih2, const float* __restrict__ bhh2,
                  float* __restrict__ out)
{
    __shared__ __align__(16) float xs[NB][T_STEPS];      // 16 KB: x slab for this block
    __shared__ __align__(16) float h1s[2][NB][H1DIM];    // double-buffered layer1 state
    __shared__ __align__(16) float h2s[2][NB][H2DIM];    // double-buffered layer2 state

    const int tid = threadIdx.x;
    const int b0  = blockIdx.x * NB;

    // --- load x slab (coalesced float4) + zero h buffers ---
    for (int i = tid; i < NB * T_STEPS / 4; i += NTHREADS) {
        int row = i / (T_STEPS / 4);
        int col = i % (T_STEPS / 4);
        reinterpret_cast<float4*>(xs[row])[col] =
            reinterpret_cast<const float4*>(x + (size_t)(b0 + row) * T_STEPS)[col];
    }
    for (int i = tid; i < 2 * NB * H1DIM; i += NTHREADS) (&h1s[0][0][0])[i] = 0.0f;
    for (int i = tid; i < 2 * NB * H2DIM; i += NTHREADS) (&h2s[0][0][0])[i] = 0.0f;
    __syncthreads();

    if (tid < 128) {
        // ================= LAYER 1 =================
        // thread = (j, kh): j in [0,64), kh in {0,1}. k pairs INTERLEAVED: {kh+2p}.
        // lanes 2m / 2m+1 are the (kh=0, kh=1) pair -> shfl_xor(1) reduce.
        const int kh = tid & 1;
        const int j  = tid >> 1;

        uint64_t w1[3][16];
        #pragma unroll
        for (int g = 0; g < 3; g++) {
            const float* row = Whh1 + (size_t)(j + 64 * g) * 64;
            #pragma unroll
            for (int p = 0; p < 16; p++)
                w1[g][p] = *reinterpret_cast<const uint64_t*>(row + 2 * (kh + 2 * p));
        }
        const float wir = Wih1[j], wiz = Wih1[j + 64], win = Wih1[j + 128];
        const float br  = bih1[j]      + bhh1[j];
        const float bz  = bih1[j + 64] + bhh1[j + 64];
        const float bni = bih1[j + 128];
        const float bnh = bhh1[j + 128];

        int rp = 0;
        for (int it = 0; it <= T_STEPS; ++it) {
            if (it < T_STEPS) {
                #pragma unroll 2
                for (int b = 0; b < NB; b++) {
                    uint64_t aR = 0, aZ = 0, aN = 0;
                    #pragma unroll
                    for (int p = 0; p < 16; p++) {
                        uint64_t hv = *reinterpret_cast<const uint64_t*>(
                            &h1s[rp][b][2 * (kh + 2 * p)]);
                        fma2(aR, w1[0][p], hv);
                        fma2(aZ, w1[1][p], hv);
                        fma2(aN, w1[2][p], hv);
                    }
                    float sR = hadd2(aR); sR += __shfl_xor_sync(0xffffffffu, sR, 1);
                    float sZ = hadd2(aZ); sZ += __shfl_xor_sync(0xffffffffu, sZ, 1);
                    float sN = hadd2(aN); sN += __shfl_xor_sync(0xffffffffu, sN, 1);
                    if (kh == (b & 1)) {   // each lane finalizes 2 of 4 batches
                        float xv  = xs[b][it];
                        float r   = sigf(fmaf(wir, xv, sR + br));
                        float z   = sigf(fmaf(wiz, xv, sZ + bz));
                        float gxn = fmaf(win, xv, bni);
                        float n   = tanhf_fast(fmaf(r, sN + bnh, gxn));
                        float ho  = h1s[rp][b][j];
                        h1s[rp ^ 1][b][j] = n + z * (ho - n);
                    }
                }
            }
            barrier_all();
            rp ^= 1;
        }
    } else {
        // ================= LAYER 2 (one step behind) =================
        // thread = (j2, s): j2 in [0,32), s in [0,4). k pairs INTERLEAVED: {s+4p}.
        // lanes 4m..4m+3 share j2 -> shfl_xor(1), shfl_xor(2) reduce within quad.
        const int t2 = tid - 128;
        const int s  = t2 & 3;
        const int j2 = t2 >> 2;

        uint64_t wI[3][8], wH[3][4];
        #pragma unroll
        for (int g = 0; g < 3; g++) {
            const float* ri = Wih2 + (size_t)(j2 + 32 * g) * 64;
            #pragma unroll
            for (int p = 0; p < 8; p++)
                wI[g][p] = *reinterpret_cast<const uint64_t*>(ri + 2 * (s + 4 * p));
            const float* rh = Whh2 + (size_t)(j2 + 32 * g) * 32;
            #pragma unroll
            for (int p = 0; p < 4; p++)
                wH[g][p] = *reinterpret_cast<const uint64_t*>(rh + 2 * (s + 4 * p));
        }
        const float br2  = bih2[j2]      + bhh2[j2];
        const float bz2  = bih2[j2 + 32] + bhh2[j2 + 32];
        const float bn2i = bih2[j2 + 64];
        const float bn2h = bhh2[j2 + 64];

        int rp = 0, q = 0;
        for (int it = 0; it <= T_STEPS; ++it) {
            if (it >= 1) {
                // processes timestep it-1: input h1[it-1] = h1s[rp], state h2s[q]
                #pragma unroll 2
                for (int b = 0; b < NB; b++) {
                    uint64_t aR = 0, aZ = 0, aNI = 0, aNH = 0;
                    #pragma unroll
                    for (int p = 0; p < 8; p++) {
                        uint64_t hv = *reinterpret_cast<const uint64_t*>(
                            &h1s[rp][b][2 * (s + 4 * p)]);
                        fma2(aR,  wI[0][p], hv);
                        fma2(aZ,  wI[1][p], hv);
                        fma2(aNI, wI[2][p], hv);
                    }
                    #pragma unroll
                    for (int p = 0; p < 4; p++) {
                        uint64_t hv = *reinterpret_cast<const uint64_t*>(
                            &h2s[q][b][2 * (s + 4 * p)]);
                        fma2(aR,  wH[0][p], hv);
                        fma2(aZ,  wH[1][p], hv);
                        fma2(aNH, wH[2][p], hv);
                    }
                    float sR  = hadd2(aR);
                    sR  += __shfl_xor_sync(0xffffffffu, sR, 1);
                    sR  += __shfl_xor_sync(0xffffffffu, sR, 2);
                    float sZ  = hadd2(aZ);
                    sZ  += __shfl_xor_sync(0xffffffffu, sZ, 1);
                    sZ  += __shfl_xor_sync(0xffffffffu, sZ, 2);
                    float sNI = hadd2(aNI);
                    sNI += __shfl_xor_sync(0xffffffffu, sNI, 1);
                    sNI += __shfl_xor_sync(0xffffffffu, sNI, 2);
                    float sNH = hadd2(aNH);
                    sNH += __shfl_xor_sync(0xffffffffu, sNH, 1);
                    sNH += __shfl_xor_sync(0xffffffffu, sNH, 2);
                    if (s == b) {           // each lane finalizes 1 of 4 batches
                        float r  = sigf(sR + br2);
                        float z  = sigf(sZ + bz2);
                        float n  = tanhf_fast(sNI + bn2i + r * (sNH + bn2h));
                        float ho = h2s[q][b][j2];
                        float hn = n + z * (ho - n);
                        h2s[q ^ 1][b][j2] = hn;
                        if (it == T_STEPS)
                            out[(size_t)(b0 + b) * H2DIM + j2] = hn;
                    }
                }
            }
            barrier_all();
            rp ^= 1;
            q  ^= 1;
        }
    }
}

extern "C" void kernel_launch(void* const* d_in, const int* in_sizes, int n_in,
                              void* d_out, int out_size) {
    const float* x    = (const float*)d_in[0];   // [1024,1024]
    const float* Wih1 = (const float*)d_in[1];   // [192,1]
    const float* Whh1 = (const float*)d_in[2];   // [192,64]
    const float* bih1 = (const float*)d_in[3];   // [192]
    const float* bhh1 = (const float*)d_in[4];   // [192]
    const float* Wih2 = (const float*)d_in[5];   // [96,64]
    const float* Whh2 = (const float*)d_in[6];   // [96,32]
    const float* bih2 = (const float*)d_in[7];   // [96]
    const float* bhh2 = (const float*)d_in[8];   // [96]
    float* out = (float*)d_out;                  // [1024,32]

    gru2_fused_kernel<<<NBATCH / NB, NTHREADS>>>(
        x, Wih1, Whh1, bih1, bhh1, Wih2, Whh2, bih2, bhh2, out);
}